// round 14
// baseline (speedup 1.0000x reference)
#include <cuda_runtime.h>
#include <cuda_fp16.h>
#include <cstdint>

#define IN_CH  512
#define HID    16
#define OUT_CH 64
#define MAX_NODES 100352
#define MAX_EDGES 3276800

// ---- scratch (device globals; no allocation allowed) ----
__device__ float  g_deg  [MAX_NODES];
__device__ float  g_dinv [MAX_NODES];
__device__ __half g_h1h  [MAX_NODES * HID];  // fp16 dinv-prescaled x@W1 (3.2MB, L2-resident)
__device__ __half g_zh   [MAX_NODES * HID];  // fp16 dinv*relu(dinv*agg1+b1)
__device__ __half g_agg1h[MAX_NODES * HID];  // fp16 accumulation buffers
__device__ __half g_agg2h[MAX_NODES * HID];

// 128-bit fp16x2 reduction: 8 halves in ONE red-lane-op (the scatter currency)
__device__ __forceinline__ void red_add_v4h2(__half* p, uint32_t r0, uint32_t r1,
                                             uint32_t r2, uint32_t r3) {
    asm volatile("red.global.add.noftz.v4.f16x2 [%0], {%1,%2,%3,%4};"
                 :: "l"(p), "r"(r0), "r"(r1), "r"(r2), "r"(r3) : "memory");
}

__device__ __forceinline__ void cp_async16(uint32_t dst, const void* src) {
    asm volatile("cp.async.cg.shared.global [%0], [%1], 16;" :: "r"(dst), "l"(src));
}

__device__ __forceinline__ uint32_t f2tf32(float f) {
    uint32_t r;
    asm("cvt.rna.tf32.f32 %0, %1;" : "=r"(r) : "f"(f));
    return r;
}

// D += A(16x8) * B(8x8), tf32 inputs, fp32 accum
__device__ __forceinline__ void mma_tf32(float* c, uint32_t a0, uint32_t a1,
                                         uint32_t a2, uint32_t a3,
                                         uint32_t b0, uint32_t b1) {
    asm volatile("mma.sync.aligned.m16n8k8.row.col.f32.tf32.tf32.f32 "
                 "{%0,%1,%2,%3}, {%4,%5,%6,%7}, {%8,%9}, {%0,%1,%2,%3};"
                 : "+f"(c[0]), "+f"(c[1]), "+f"(c[2]), "+f"(c[3])
                 : "r"(a0), "r"(a1), "r"(a2), "r"(a3), "r"(b0), "r"(b1));
}

// ---------------------------------------------------------------- zero (agg1h + deg)
__global__ void zero_kernel(int n) {
    int i = blockIdx.x * blockDim.x + threadIdx.x;
    int t4 = n * HID / 8;            // uint4 = 8 halves
    if (i < t4) ((uint4*)g_agg1h)[i] = make_uint4(0u, 0u, 0u, 0u);
    if (i < n) g_deg[i] = 0.f;
}

// ---------------------------------------------------------------- degree
__global__ void deg_kernel(const int* __restrict__ ei1, const float* __restrict__ w1, int E1,
                           const int* __restrict__ ei2, const float* __restrict__ w2, int E2) {
    int i = blockIdx.x * blockDim.x + threadIdx.x;
    if (i < E1) {
        atomicAdd(&g_deg[ei1[i]], w1[i]);
    } else {
        int j = i - E1;
        if (j < E2) atomicAdd(&g_deg[ei2[j]], w2[j]);
    }
}

__global__ void dinv_kernel(int n) {
    int i = blockIdx.x * blockDim.x + threadIdx.x;
    if (i >= n) return;
    float d = g_deg[i];
    g_dinv[i] = d > 0.f ? rsqrtf(fmaxf(d, 1e-12f)) : 0.f;
}

// ---------------------------------------------------------------- h1h = fp16(dinv .* (x @ W1))  [tf32 tensor cores]
// warp = 16 nodes, 2 mma n-tiles, K=512 in 64 k8-steps. KC=16 floats/chunk
// -> 48KB smem/block -> 4 blocks/SM (32 warps, occ 50%) to hide cp.async
// latency. XOR swizzle c4^((r>>1)&3): conflict-free for STS.128 staging and
// scalar A-frag LDS (bank = 16(r&1) + 4(c4^s) + k0, injective per warp).
#define GM_THREADS 256
#define GM_WARPS   8
#define GM_NPW     16
#define GM_TILE    (GM_WARPS * GM_NPW)      // 128 nodes per block
#define GM_KC      16                       // floats per chunk per row
#define GM_NCHUNK  (IN_CH / GM_KC)          // 32
#define GM_BUF     (GM_NPW * GM_KC)         // 256 floats per buffer (1024 bytes)
#define GM_WF_FLOATS (64 * 2 * 32 * 2)      // 8192 floats = 32KB
#define GM_SMEM_FLOATS (GM_WF_FLOATS + GM_WARPS * 2 * GM_BUF)  // 48KB

__global__ void __launch_bounds__(GM_THREADS, 4)
gemm1_kernel(const float* __restrict__ x, const float* __restrict__ W1, int n) {
    extern __shared__ float smem[];
    float2* Wf = (float2*)smem;             // [ks(64)][tile(2)][lane(32)] -> (b0,b1)
    const int warp = threadIdx.x >> 5;
    const int lane = threadIdx.x & 31;
    float* xb = smem + GM_WF_FLOATS + warp * (2 * GM_BUF);
    const uint32_t xb_s = (uint32_t)__cvta_generic_to_shared(xb);

    // pack W1 into tf32 B fragments: b0 = B[k, n], b1 = B[k+4, n]
    for (int i = threadIdx.x; i < 64 * 2 * 32; i += GM_THREADS) {
        int li = i & 31, tile = (i >> 5) & 1, ks = i >> 6;
        int k = ks * 8 + (li & 3);
        int ncol = tile * 8 + (li >> 2);
        uint32_t b0 = f2tf32(__ldg(W1 + k * HID + ncol));
        uint32_t b1 = f2tf32(__ldg(W1 + (k + 4) * HID + ncol));
        Wf[i] = make_float2(__uint_as_float(b0), __uint_as_float(b1));
    }
    __syncthreads();

    const int nodebase = blockIdx.x * GM_TILE + warp * GM_NPW;
    const int row0 = lane >> 2, row1 = row0 + 8;
    const int k0 = lane & 3;

    // staging: 64 float4 per chunk (16 rows x 4 slots), 2 per lane
    uint32_t st_dst[2];
    const float4* st_src[2];
#pragma unroll
    for (int t = 0; t < 2; t++) {
        int idx = t * 32 + lane;            // 0..63
        int r = idx >> 2, c4 = idx & 3;
        st_dst[t] = xb_s + 16u * (r * 4 + (c4 ^ ((r >> 1) & 3)));
        int nd = nodebase + r;
        st_src[t] = (const float4*)x + ((nd < n) ? (size_t)nd * (IN_CH / 4) : 0) + c4;
    }

    float acc[8];                            // tile0: 0-3, tile1: 4-7
#pragma unroll
    for (int j = 0; j < 8; j++) acc[j] = 0.f;

    // prefetch chunk 0 into buffer 0
    cp_async16(st_dst[0], st_src[0]);
    cp_async16(st_dst[1], st_src[1]);
    asm volatile("cp.async.commit_group;" ::: "memory");

    // A-frag smem float offsets (swizzled); row1 = row0+8 shares the same
    // swizzle constant since ((row0+8)>>1)&3 == (row0>>1)&3
    const int aoff0 = row0 * GM_KC;
    const int aoff1 = row1 * GM_KC;
    const int rs = (row0 >> 1) & 3;

    for (int c = 0; c < GM_NCHUNK; c++) {
        if (c + 1 < GM_NCHUNK) {
            const uint32_t nb_off = ((c + 1) & 1) * (GM_BUF * 4u);   // bytes: 0 or 1024
            const int nk4 = (c + 1) * (GM_KC / 4);
            cp_async16(st_dst[0] + nb_off, st_src[0] + nk4);
            cp_async16(st_dst[1] + nb_off, st_src[1] + nk4);
            asm volatile("cp.async.commit_group;" ::: "memory");
            asm volatile("cp.async.wait_group 1;" ::: "memory");
        } else {
            asm volatile("cp.async.wait_group 0;" ::: "memory");
        }
        __syncwarp();

        const float* xc = xb + (c & 1) * GM_BUF;
#pragma unroll
        for (int ks = 0; ks < 2; ks++) {
            const int c4a = 2 * ks, c4b = 2 * ks + 1;
            // A fragment: a0=(row0,k), a1=(row1,k), a2=(row0,k+4), a3=(row1,k+4)
            uint32_t a0 = f2tf32(xc[aoff0 + ((c4a ^ rs) << 2) + k0]);
            uint32_t a1 = f2tf32(xc[aoff1 + ((c4a ^ rs) << 2) + k0]);
            uint32_t a2 = f2tf32(xc[aoff0 + ((c4b ^ rs) << 2) + k0]);
            uint32_t a3 = f2tf32(xc[aoff1 + ((c4b ^ rs) << 2) + k0]);
            const int ksg = c * 2 + ks;
            float2 bA = Wf[(ksg * 2 + 0) * 32 + lane];
            float2 bB = Wf[(ksg * 2 + 1) * 32 + lane];
            mma_tf32(acc,     a0, a1, a2, a3,
                     __float_as_uint(bA.x), __float_as_uint(bA.y));
            mma_tf32(acc + 4, a0, a1, a2, a3,
                     __float_as_uint(bB.x), __float_as_uint(bB.y));
        }
        __syncwarp();
    }

    // epilogue: C layout c0=(row, 2k0), c1=(row, 2k0+1), c2=(row+8, 2k0), c3=(row+8, 2k0+1)
    const int node0 = nodebase + row0;
    const int node1 = nodebase + row1;
    if (node0 < n) {
        float dv = __ldg(g_dinv + node0);
        __half2 t0 = __floats2half2_rn(acc[0] * dv, acc[1] * dv);
        __half2 t1 = __floats2half2_rn(acc[4] * dv, acc[5] * dv);
        *(uint32_t*)(g_h1h + (size_t)node0 * HID + 2 * k0)     = *(uint32_t*)&t0;
        *(uint32_t*)(g_h1h + (size_t)node0 * HID + 8 + 2 * k0) = *(uint32_t*)&t1;
    }
    if (node1 < n) {
        float dv = __ldg(g_dinv + node1);
        __half2 t0 = __floats2half2_rn(acc[2] * dv, acc[3] * dv);
        __half2 t1 = __floats2half2_rn(acc[6] * dv, acc[7] * dv);
        *(uint32_t*)(g_h1h + (size_t)node1 * HID + 2 * k0)     = *(uint32_t*)&t0;
        *(uint32_t*)(g_h1h + (size_t)node1 * HID + 8 + 2 * k0) = *(uint32_t*)&t1;
    }
}

// ---------------------------------------------------------------- scatter (fp16 reds)
// 2 lanes per edge, each: gather 16B (8 halves), scale by w (half2), ONE
// red.v4.f16x2 (8 halves, 128-bit) -> 6.4M red-lane-ops (the floor: 2 per
// edge at 128-bit max red width).
template <int LAYER>
__global__ void scatter_kernel(const int* __restrict__ ei1, const float* __restrict__ w1, int E1,
                               const int* __restrict__ ei2, const float* __restrict__ w2, int E2) {
    int t = blockIdx.x * blockDim.x + threadIdx.x;
    int e   = t >> 1;
    int sub = t & 1;
    int row, col;
    float w;
    if (e < E1) {
        row = __ldg(ei1 + e); col = __ldg(ei1 + E1 + e); w = __ldg(w1 + e);
    } else {
        int j = e - E1;
        if (j >= E2) return;
        row = __ldg(ei2 + j); col = __ldg(ei2 + E2 + j); w = __ldg(w2 + j);
    }

    const __half* src = (LAYER == 1) ? g_h1h : g_zh;
    __half*       dst = (LAYER == 1) ? g_agg1h : g_agg2h;

    uint4 hv = __ldg((const uint4*)(src + (size_t)col * HID + sub * 8));
    __half2 w2h = __float2half2_rn(w);
    __half2 h0 = __hmul2(*(__half2*)&hv.x, w2h);
    __half2 h1 = __hmul2(*(__half2*)&hv.y, w2h);
    __half2 h2 = __hmul2(*(__half2*)&hv.z, w2h);
    __half2 h3 = __hmul2(*(__half2*)&hv.w, w2h);

    red_add_v4h2(dst + (size_t)row * HID + sub * 8,
                 *(uint32_t*)&h0, *(uint32_t*)&h1, *(uint32_t*)&h2, *(uint32_t*)&h3);
}

// ---------------------------------------------------------------- zh = fp16(dinv.*relu(dinv.*agg1h + b1)); zero agg2h
__global__ void relu_kernel(const float* __restrict__ b1, int n) {
    int i = blockIdx.x * blockDim.x + threadIdx.x;
    if (i >= 2 * n) return;
    int node = i >> 1, sub = i & 1;
    float dv = __ldg(g_dinv + node);
    uint4 u = ((const uint4*)(g_agg1h))[i];
    const float4* bb = (const float4*)(b1 + sub * 8);
    float4 b0 = __ldg(bb), b1v = __ldg(bb + 1);
    float2 f0 = __half22float2(*(__half2*)&u.x);
    float2 f1 = __half22float2(*(__half2*)&u.y);
    float2 f2 = __half22float2(*(__half2*)&u.z);
    float2 f3 = __half22float2(*(__half2*)&u.w);
    f0.x = dv * fmaxf(dv * f0.x + b0.x, 0.f);  f0.y = dv * fmaxf(dv * f0.y + b0.y, 0.f);
    f1.x = dv * fmaxf(dv * f1.x + b0.z, 0.f);  f1.y = dv * fmaxf(dv * f1.y + b0.w, 0.f);
    f2.x = dv * fmaxf(dv * f2.x + b1v.x, 0.f); f2.y = dv * fmaxf(dv * f2.y + b1v.y, 0.f);
    f3.x = dv * fmaxf(dv * f3.x + b1v.z, 0.f); f3.y = dv * fmaxf(dv * f3.y + b1v.w, 0.f);
    __half2 h0 = __floats2half2_rn(f0.x, f0.y);
    __half2 h1 = __floats2half2_rn(f1.x, f1.y);
    __half2 h2 = __floats2half2_rn(f2.x, f2.y);
    __half2 h3 = __floats2half2_rn(f3.x, f3.y);
    ((uint4*)g_zh)[i] = make_uint4(*(unsigned*)&h0, *(unsigned*)&h1,
                                   *(unsigned*)&h2, *(unsigned*)&h3);
    ((uint4*)g_agg2h)[i] = make_uint4(0u, 0u, 0u, 0u);
}

// ---------------------------------------------------------------- out = log_softmax((dinv.*agg2h) @ W2 + b2)
#define OUT_WARPS 8
__global__ void out_kernel(const float* __restrict__ W2, const float* __restrict__ b2,
                           float* __restrict__ out, int n) {
    __shared__ float W2s[HID * OUT_CH];
    for (int t = threadIdx.x; t < HID * OUT_CH / 4; t += blockDim.x)
        ((float4*)W2s)[t] = ((const float4*)W2)[t];
    __syncthreads();

    int warp = threadIdx.x >> 5, lane = threadIdx.x & 31;
    int node = blockIdx.x * OUT_WARPS + warp;
    if (node >= n) return;

    float dv = __ldg(g_dinv + node);
    const uint4* a4 = (const uint4*)(g_agg2h + (size_t)node * HID);
    uint4 u0 = __ldg(a4), u1 = __ldg(a4 + 1);
    float a[16];
    {
        float2 f;
        f = __half22float2(*(__half2*)&u0.x); a[0]  = f.x; a[1]  = f.y;
        f = __half22float2(*(__half2*)&u0.y); a[2]  = f.x; a[3]  = f.y;
        f = __half22float2(*(__half2*)&u0.z); a[4]  = f.x; a[5]  = f.y;
        f = __half22float2(*(__half2*)&u0.w); a[6]  = f.x; a[7]  = f.y;
        f = __half22float2(*(__half2*)&u1.x); a[8]  = f.x; a[9]  = f.y;
        f = __half22float2(*(__half2*)&u1.y); a[10] = f.x; a[11] = f.y;
        f = __half22float2(*(__half2*)&u1.z); a[12] = f.x; a[13] = f.y;
        f = __half22float2(*(__half2*)&u1.w); a[14] = f.x; a[15] = f.y;
    }
#pragma unroll
    for (int k = 0; k < HID; k++) a[k] *= dv;

    float acc0 = b2[lane];
    float acc1 = b2[lane + 32];
#pragma unroll
    for (int k = 0; k < HID; k++) {
        acc0 += a[k] * W2s[k * OUT_CH + lane];
        acc1 += a[k] * W2s[k * OUT_CH + lane + 32];
    }

    float m = fmaxf(acc0, acc1);
#pragma unroll
    for (int off = 16; off >= 1; off >>= 1)
        m = fmaxf(m, __shfl_xor_sync(0xffffffffu, m, off));
    float s = expf(acc0 - m) + expf(acc1 - m);
#pragma unroll
    for (int off = 16; off >= 1; off >>= 1)
        s += __shfl_xor_sync(0xffffffffu, s, off);
    float lse = m + logf(s);

    out[(size_t)node * OUT_CH + lane]      = acc0 - lse;
    out[(size_t)node * OUT_CH + lane + 32] = acc1 - lse;
}

// ---------------------------------------------------------------- launch
extern "C" void kernel_launch(void* const* d_in, const int* in_sizes, int n_in,
                              void* d_out, int out_size) {
    const float* x   = (const float*)d_in[0];
    const int*   ei1 = (const int*)  d_in[1];
    const float* ew1 = (const float*)d_in[2];
    const int*   ei2 = (const int*)  d_in[3];
    const float* ew2 = (const float*)d_in[4];
    const float* W1  = (const float*)d_in[5];
    const float* b1  = (const float*)d_in[6];
    const float* W2  = (const float*)d_in[7];
    const float* b2  = (const float*)d_in[8];
    float* out = (float*)d_out;

    int n  = in_sizes[0] / IN_CH;
    int E1 = in_sizes[2];
    int E2 = in_sizes[4];
    int Et = E1 + E2;

    const int GM_SMEM = GM_SMEM_FLOATS * (int)sizeof(float);
    cudaFuncSetAttribute(gemm1_kernel, cudaFuncAttributeMaxDynamicSharedMemorySize, GM_SMEM);

    zero_kernel<<<(n * HID / 8 + 255) / 256, 256>>>(n);
    deg_kernel<<<(Et + 255) / 256, 256>>>(ei1, ew1, E1, ei2, ew2, E2);
    dinv_kernel<<<(n + 255) / 256, 256>>>(n);
    gemm1_kernel<<<(n + GM_TILE - 1) / GM_TILE, GM_THREADS, GM_SMEM>>>(x, W1, n);
    scatter_kernel<1><<<(2 * Et + 255) / 256, 256>>>(ei1, ew1, E1, ei2, ew2, E2);
    relu_kernel<<<(2 * n + 255) / 256, 256>>>(b1, n);
    scatter_kernel<2><<<(2 * Et + 255) / 256, 256>>>(ei1, ew1, E1, ei2, ew2, E2);
    out_kernel<<<(n + OUT_WARPS - 1) / OUT_WARPS, OUT_WARPS * 32>>>(W2, b2, out, n);
}

// round 15
// speedup vs baseline: 1.0301x; 1.0301x over previous
#include <cuda_runtime.h>
#include <cuda_fp16.h>
#include <cstdint>

#define IN_CH  512
#define HID    16
#define OUT_CH 64
#define MAX_NODES 100352
#define MAX_EDGES 3276800

// ---- scratch (device globals; no allocation allowed) ----
__device__ float  g_deg  [MAX_NODES];
__device__ float  g_dinv [MAX_NODES];
__device__ __half g_h1h  [MAX_NODES * HID];  // fp16 x@W1 (unscaled, then dinv-scaled by prep)
__device__ __half g_zh   [MAX_NODES * HID];  // fp16 dinv*relu(dinv*agg1+b1)
__device__ __half g_agg1h[MAX_NODES * HID];  // fp16 accumulation buffers
__device__ __half g_agg2h[MAX_NODES * HID];

// 128-bit fp16x2 reduction: 8 halves in ONE red-lane-op (the scatter currency)
__device__ __forceinline__ void red_add_v4h2(__half* p, uint32_t r0, uint32_t r1,
                                             uint32_t r2, uint32_t r3) {
    asm volatile("red.global.add.noftz.v4.f16x2 [%0], {%1,%2,%3,%4};"
                 :: "l"(p), "r"(r0), "r"(r1), "r"(r2), "r"(r3) : "memory");
}

__device__ __forceinline__ void cp_async16(uint32_t dst, const void* src) {
    asm volatile("cp.async.cg.shared.global [%0], [%1], 16;" :: "r"(dst), "l"(src));
}

__device__ __forceinline__ uint32_t f2tf32(float f) {
    uint32_t r;
    asm("cvt.rna.tf32.f32 %0, %1;" : "=r"(r) : "f"(f));
    return r;
}

// D += A(16x8) * B(8x8), tf32 inputs, fp32 accum
__device__ __forceinline__ void mma_tf32(float* c, uint32_t a0, uint32_t a1,
                                         uint32_t a2, uint32_t a3,
                                         uint32_t b0, uint32_t b1) {
    asm volatile("mma.sync.aligned.m16n8k8.row.col.f32.tf32.tf32.f32 "
                 "{%0,%1,%2,%3}, {%4,%5,%6,%7}, {%8,%9}, {%0,%1,%2,%3};"
                 : "+f"(c[0]), "+f"(c[1]), "+f"(c[2]), "+f"(c[3])
                 : "r"(a0), "r"(a1), "r"(a2), "r"(a3), "r"(b0), "r"(b1));
}

// ---------------------------------------------------------------- zero deg (side stream)
__global__ void zero_deg_kernel(int n) {
    int i = blockIdx.x * blockDim.x + threadIdx.x;
    if (i < n) g_deg[i] = 0.f;
}

// ---------------------------------------------------------------- degree (side stream)
__global__ void deg_kernel(const int* __restrict__ ei1, const float* __restrict__ w1, int E1,
                           const int* __restrict__ ei2, const float* __restrict__ w2, int E2) {
    int i = blockIdx.x * blockDim.x + threadIdx.x;
    if (i < E1) {
        atomicAdd(&g_deg[ei1[i]], w1[i]);
    } else {
        int j = i - E1;
        if (j < E2) atomicAdd(&g_deg[ei2[j]], w2[j]);
    }
}

__global__ void dinv_kernel(int n) {
    int i = blockIdx.x * blockDim.x + threadIdx.x;
    if (i >= n) return;
    float d = g_deg[i];
    g_dinv[i] = d > 0.f ? rsqrtf(fmaxf(d, 1e-12f)) : 0.f;
}

// ---------------------------------------------------------------- h1h = fp16(x @ W1)  [tf32 tensor cores, UNSCALED]
// R13 champion shape: warp = 16 nodes, 2 mma n-tiles, KC=32 floats/chunk,
// cp.async double-buffered, 64KB smem -> 3 blocks/SM. dinv dependency removed
// (scaling moved to prep_kernel) so this can overlap deg/dinv on a side stream.
#define GM_THREADS 256
#define GM_WARPS   8
#define GM_NPW     16
#define GM_TILE    (GM_WARPS * GM_NPW)      // 128 nodes per block
#define GM_KC      32                       // floats per chunk
#define GM_NCHUNK  (IN_CH / GM_KC)          // 16
#define GM_BUF     (GM_NPW * GM_KC)         // 512 floats per buffer (2048 bytes)
#define GM_WF_FLOATS (64 * 2 * 32 * 2)      // 8192 floats = 32KB
#define GM_SMEM_FLOATS (GM_WF_FLOATS + GM_WARPS * 2 * GM_BUF)  // 64KB

__global__ void __launch_bounds__(GM_THREADS, 3)
gemm1_kernel(const float* __restrict__ x, const float* __restrict__ W1, int n) {
    extern __shared__ float smem[];
    float2* Wf = (float2*)smem;             // [ks(64)][tile(2)][lane(32)] -> (b0,b1)
    const int warp = threadIdx.x >> 5;
    const int lane = threadIdx.x & 31;
    float* xb = smem + GM_WF_FLOATS + warp * (2 * GM_BUF);
    const uint32_t xb_s = (uint32_t)__cvta_generic_to_shared(xb);

    // pack W1 into tf32 B fragments: b0 = B[k, n], b1 = B[k+4, n]
    for (int i = threadIdx.x; i < 64 * 2 * 32; i += GM_THREADS) {
        int li = i & 31, tile = (i >> 5) & 1, ks = i >> 6;
        int k = ks * 8 + (li & 3);
        int ncol = tile * 8 + (li >> 2);
        uint32_t b0 = f2tf32(__ldg(W1 + k * HID + ncol));
        uint32_t b1 = f2tf32(__ldg(W1 + (k + 4) * HID + ncol));
        Wf[i] = make_float2(__uint_as_float(b0), __uint_as_float(b1));
    }
    __syncthreads();

    const int nodebase = blockIdx.x * GM_TILE + warp * GM_NPW;
    const int row0 = lane >> 2, row1 = row0 + 8;
    const int k0 = lane & 3;

    // staging: 128 float4 per chunk (16 rows x 8 slots), 4 per lane
    uint32_t st_dst[4];
    const float4* st_src[4];
#pragma unroll
    for (int t = 0; t < 4; t++) {
        int idx = t * 32 + lane;            // 0..127
        int r = idx >> 3, c4 = idx & 7;
        st_dst[t] = xb_s + 16u * (r * 8 + (c4 ^ (r & 7)));
        int nd = nodebase + r;
        st_src[t] = (const float4*)x + ((nd < n) ? (size_t)nd * (IN_CH / 4) : 0) + c4;
    }

    float acc[8];                            // tile0: 0-3, tile1: 4-7
#pragma unroll
    for (int j = 0; j < 8; j++) acc[j] = 0.f;

    // prefetch chunk 0 into buffer 0
#pragma unroll
    for (int t = 0; t < 4; t++) cp_async16(st_dst[t], st_src[t]);
    asm volatile("cp.async.commit_group;" ::: "memory");

    // A-frag smem float offsets (swizzled), constant across chunks except ks
    const int aoff0 = row0 * GM_KC;
    const int aoff1 = row1 * GM_KC;
    const int rs0 = row0 & 7;                // == row1 & 7

    for (int c = 0; c < GM_NCHUNK; c++) {
        if (c + 1 < GM_NCHUNK) {
            const uint32_t nb_off = ((c + 1) & 1) * (GM_BUF * 4u);   // bytes: 0 or 2048
#pragma unroll
            for (int t = 0; t < 4; t++)
                cp_async16(st_dst[t] + nb_off, st_src[t] + (c + 1) * (GM_KC / 4));
            asm volatile("cp.async.commit_group;" ::: "memory");
            asm volatile("cp.async.wait_group 1;" ::: "memory");
        } else {
            asm volatile("cp.async.wait_group 0;" ::: "memory");
        }
        __syncwarp();

        const float* xc = xb + (c & 1) * GM_BUF;
#pragma unroll
        for (int ks = 0; ks < 4; ks++) {
            const int c4a = 2 * ks, c4b = 2 * ks + 1;
            // A fragment: a0=(row0,k), a1=(row1,k), a2=(row0,k+4), a3=(row1,k+4)
            uint32_t a0 = f2tf32(xc[aoff0 + ((c4a ^ rs0) << 2) + k0]);
            uint32_t a1 = f2tf32(xc[aoff1 + ((c4a ^ rs0) << 2) + k0]);
            uint32_t a2 = f2tf32(xc[aoff0 + ((c4b ^ rs0) << 2) + k0]);
            uint32_t a3 = f2tf32(xc[aoff1 + ((c4b ^ rs0) << 2) + k0]);
            const int ksg = c * 4 + ks;
            float2 bA = Wf[(ksg * 2 + 0) * 32 + lane];
            float2 bB = Wf[(ksg * 2 + 1) * 32 + lane];
            mma_tf32(acc,     a0, a1, a2, a3,
                     __float_as_uint(bA.x), __float_as_uint(bA.y));
            mma_tf32(acc + 4, a0, a1, a2, a3,
                     __float_as_uint(bB.x), __float_as_uint(bB.y));
        }
        __syncwarp();
    }

    // epilogue (UNSCALED): c0=(row, 2k0), c1=(row, 2k0+1), c2=(row+8, ..), c3=(row+8, ..)
    const int node0 = nodebase + row0;
    const int node1 = nodebase + row1;
    if (node0 < n) {
        __half2 t0 = __floats2half2_rn(acc[0], acc[1]);
        __half2 t1 = __floats2half2_rn(acc[4], acc[5]);
        *(uint32_t*)(g_h1h + (size_t)node0 * HID + 2 * k0)     = *(uint32_t*)&t0;
        *(uint32_t*)(g_h1h + (size_t)node0 * HID + 8 + 2 * k0) = *(uint32_t*)&t1;
    }
    if (node1 < n) {
        __half2 t0 = __floats2half2_rn(acc[2], acc[3]);
        __half2 t1 = __floats2half2_rn(acc[6], acc[7]);
        *(uint32_t*)(g_h1h + (size_t)node1 * HID + 2 * k0)     = *(uint32_t*)&t0;
        *(uint32_t*)(g_h1h + (size_t)node1 * HID + 8 + 2 * k0) = *(uint32_t*)&t1;
    }
}

// ---------------------------------------------------------------- prep (join point):
// h1h *= dinv[node] (fp32 math), zero agg1h. One thread per half-node.
__global__ void prep_kernel(int n) {
    int i = blockIdx.x * blockDim.x + threadIdx.x;
    if (i >= 2 * n) return;
    int node = i >> 1;
    float dv = __ldg(g_dinv + node);
    uint4 u = ((const uint4*)g_h1h)[i];
    float2 f0 = __half22float2(*(__half2*)&u.x);
    float2 f1 = __half22float2(*(__half2*)&u.y);
    float2 f2 = __half22float2(*(__half2*)&u.z);
    float2 f3 = __half22float2(*(__half2*)&u.w);
    __half2 h0 = __floats2half2_rn(f0.x * dv, f0.y * dv);
    __half2 h1 = __floats2half2_rn(f1.x * dv, f1.y * dv);
    __half2 h2 = __floats2half2_rn(f2.x * dv, f2.y * dv);
    __half2 h3 = __floats2half2_rn(f3.x * dv, f3.y * dv);
    ((uint4*)g_h1h)[i] = make_uint4(*(unsigned*)&h0, *(unsigned*)&h1,
                                    *(unsigned*)&h2, *(unsigned*)&h3);
    ((uint4*)g_agg1h)[i] = make_uint4(0u, 0u, 0u, 0u);
}

// ---------------------------------------------------------------- scatter (fp16 reds)
// 2 lanes per edge, each: gather 16B (8 halves), scale by w (half2), ONE
// red.v4.f16x2 -> 4 L1tex wavefronts/edge (the floor at 16B lane width).
template <int LAYER>
__global__ void scatter_kernel(const int* __restrict__ ei1, const float* __restrict__ w1, int E1,
                               const int* __restrict__ ei2, const float* __restrict__ w2, int E2) {
    int t = blockIdx.x * blockDim.x + threadIdx.x;
    int e   = t >> 1;
    int sub = t & 1;
    int row, col;
    float w;
    if (e < E1) {
        row = __ldg(ei1 + e); col = __ldg(ei1 + E1 + e); w = __ldg(w1 + e);
    } else {
        int j = e - E1;
        if (j >= E2) return;
        row = __ldg(ei2 + j); col = __ldg(ei2 + E2 + j); w = __ldg(w2 + j);
    }

    const __half* src = (LAYER == 1) ? g_h1h : g_zh;
    __half*       dst = (LAYER == 1) ? g_agg1h : g_agg2h;

    uint4 hv = __ldg((const uint4*)(src + (size_t)col * HID + sub * 8));
    __half2 w2h = __float2half2_rn(w);
    __half2 h0 = __hmul2(*(__half2*)&hv.x, w2h);
    __half2 h1 = __hmul2(*(__half2*)&hv.y, w2h);
    __half2 h2 = __hmul2(*(__half2*)&hv.z, w2h);
    __half2 h3 = __hmul2(*(__half2*)&hv.w, w2h);

    red_add_v4h2(dst + (size_t)row * HID + sub * 8,
                 *(uint32_t*)&h0, *(uint32_t*)&h1, *(uint32_t*)&h2, *(uint32_t*)&h3);
}

// ---------------------------------------------------------------- zh = fp16(dinv.*relu(dinv.*agg1h + b1)); zero agg2h
__global__ void relu_kernel(const float* __restrict__ b1, int n) {
    int i = blockIdx.x * blockDim.x + threadIdx.x;
    if (i >= 2 * n) return;
    int node = i >> 1, sub = i & 1;
    float dv = __ldg(g_dinv + node);
    uint4 u = ((const uint4*)(g_agg1h))[i];
    const float4* bb = (const float4*)(b1 + sub * 8);
    float4 b0 = __ldg(bb), b1v = __ldg(bb + 1);
    float2 f0 = __half22float2(*(__half2*)&u.x);
    float2 f1 = __half22float2(*(__half2*)&u.y);
    float2 f2 = __half22float2(*(__half2*)&u.z);
    float2 f3 = __half22float2(*(__half2*)&u.w);
    f0.x = dv * fmaxf(dv * f0.x + b0.x, 0.f);  f0.y = dv * fmaxf(dv * f0.y + b0.y, 0.f);
    f1.x = dv * fmaxf(dv * f1.x + b0.z, 0.f);  f1.y = dv * fmaxf(dv * f1.y + b0.w, 0.f);
    f2.x = dv * fmaxf(dv * f2.x + b1v.x, 0.f); f2.y = dv * fmaxf(dv * f2.y + b1v.y, 0.f);
    f3.x = dv * fmaxf(dv * f3.x + b1v.z, 0.f); f3.y = dv * fmaxf(dv * f3.y + b1v.w, 0.f);
    __half2 h0 = __floats2half2_rn(f0.x, f0.y);
    __half2 h1 = __floats2half2_rn(f1.x, f1.y);
    __half2 h2 = __floats2half2_rn(f2.x, f2.y);
    __half2 h3 = __floats2half2_rn(f3.x, f3.y);
    ((uint4*)g_zh)[i] = make_uint4(*(unsigned*)&h0, *(unsigned*)&h1,
                                   *(unsigned*)&h2, *(unsigned*)&h3);
    ((uint4*)g_agg2h)[i] = make_uint4(0u, 0u, 0u, 0u);
}

// ---------------------------------------------------------------- out = log_softmax((dinv.*agg2h) @ W2 + b2)
#define OUT_WARPS 8
__global__ void out_kernel(const float* __restrict__ W2, const float* __restrict__ b2,
                           float* __restrict__ out, int n) {
    __shared__ float W2s[HID * OUT_CH];
    for (int t = threadIdx.x; t < HID * OUT_CH / 4; t += blockDim.x)
        ((float4*)W2s)[t] = ((const float4*)W2)[t];
    __syncthreads();

    int warp = threadIdx.x >> 5, lane = threadIdx.x & 31;
    int node = blockIdx.x * OUT_WARPS + warp;
    if (node >= n) return;

    float dv = __ldg(g_dinv + node);
    const uint4* a4 = (const uint4*)(g_agg2h + (size_t)node * HID);
    uint4 u0 = __ldg(a4), u1 = __ldg(a4 + 1);
    float a[16];
    {
        float2 f;
        f = __half22float2(*(__half2*)&u0.x); a[0]  = f.x; a[1]  = f.y;
        f = __half22float2(*(__half2*)&u0.y); a[2]  = f.x; a[3]  = f.y;
        f = __half22float2(*(__half2*)&u0.z); a[4]  = f.x; a[5]  = f.y;
        f = __half22float2(*(__half2*)&u0.w); a[6]  = f.x; a[7]  = f.y;
        f = __half22float2(*(__half2*)&u1.x); a[8]  = f.x; a[9]  = f.y;
        f = __half22float2(*(__half2*)&u1.y); a[10] = f.x; a[11] = f.y;
        f = __half22float2(*(__half2*)&u1.z); a[12] = f.x; a[13] = f.y;
        f = __half22float2(*(__half2*)&u1.w); a[14] = f.x; a[15] = f.y;
    }
#pragma unroll
    for (int k = 0; k < HID; k++) a[k] *= dv;

    float acc0 = b2[lane];
    float acc1 = b2[lane + 32];
#pragma unroll
    for (int k = 0; k < HID; k++) {
        acc0 += a[k] * W2s[k * OUT_CH + lane];
        acc1 += a[k] * W2s[k * OUT_CH + lane + 32];
    }

    float m = fmaxf(acc0, acc1);
#pragma unroll
    for (int off = 16; off >= 1; off >>= 1)
        m = fmaxf(m, __shfl_xor_sync(0xffffffffu, m, off));
    float s = expf(acc0 - m) + expf(acc1 - m);
#pragma unroll
    for (int off = 16; off >= 1; off >>= 1)
        s += __shfl_xor_sync(0xffffffffu, s, off);
    float lse = m + logf(s);

    out[(size_t)node * OUT_CH + lane]      = acc0 - lse;
    out[(size_t)node * OUT_CH + lane + 32] = acc1 - lse;
}

// ---------------------------------------------------------------- launch
// Fork-join: side stream runs zero_deg -> deg -> dinv concurrently with gemm1
// (main stream). Join before prep. Streams/events are host objects created per
// call and intentionally leaked (kernel_launch only runs for correctness +
// capture; replays execute the graph, not this host code).
extern "C" void kernel_launch(void* const* d_in, const int* in_sizes, int n_in,
                              void* d_out, int out_size) {
    const float* x   = (const float*)d_in[0];
    const int*   ei1 = (const int*)  d_in[1];
    const float* ew1 = (const float*)d_in[2];
    const int*   ei2 = (const int*)  d_in[3];
    const float* ew2 = (const float*)d_in[4];
    const float* W1  = (const float*)d_in[5];
    const float* b1  = (const float*)d_in[6];
    const float* W2  = (const float*)d_in[7];
    const float* b2  = (const float*)d_in[8];
    float* out = (float*)d_out;

    int n  = in_sizes[0] / IN_CH;
    int E1 = in_sizes[2];
    int E2 = in_sizes[4];
    int Et = E1 + E2;

    const int GM_SMEM = GM_SMEM_FLOATS * (int)sizeof(float);
    cudaFuncSetAttribute(gemm1_kernel, cudaFuncAttributeMaxDynamicSharedMemorySize, GM_SMEM);

    cudaStream_t s1;
    cudaStreamCreateWithFlags(&s1, cudaStreamNonBlocking);
    cudaEvent_t ev_fork, ev_join;
    cudaEventCreateWithFlags(&ev_fork, cudaEventDisableTiming);
    cudaEventCreateWithFlags(&ev_join, cudaEventDisableTiming);

    // fork: side stream inherits main-stream ordering
    cudaEventRecord(ev_fork, 0);
    cudaStreamWaitEvent(s1, ev_fork, 0);

    // side stream: degree pipeline (atomic/LTS-bound)
    zero_deg_kernel<<<(n + 255) / 256, 256, 0, s1>>>(n);
    deg_kernel<<<(Et + 255) / 256, 256, 0, s1>>>(ei1, ew1, E1, ei2, ew2, E2);
    dinv_kernel<<<(n + 255) / 256, 256, 0, s1>>>(n);

    // main stream: gemm1 (DRAM-bound), independent of dinv now
    gemm1_kernel<<<(n + GM_TILE - 1) / GM_TILE, GM_THREADS, GM_SMEM>>>(x, W1, n);

    // join
    cudaEventRecord(ev_join, s1);
    cudaStreamWaitEvent(0, ev_join, 0);

    prep_kernel<<<(2 * n + 255) / 256, 256>>>(n);
    scatter_kernel<1><<<(2 * Et + 255) / 256, 256>>>(ei1, ew1, E1, ei2, ew2, E2);
    relu_kernel<<<(2 * n + 255) / 256, 256>>>(b1, n);
    scatter_kernel<2><<<(2 * Et + 255) / 256, 256>>>(ei1, ew1, E1, ei2, ew2, E2);
    out_kernel<<<(n + OUT_WARPS - 1) / OUT_WARPS, OUT_WARPS * 32>>>(W2, b2, out, n);
    // s1 / events intentionally leaked (see note above)
}